// round 12
// baseline (speedup 1.0000x reference)
#include <cuda_runtime.h>
#include <cuda_bf16.h>
#include <cstdint>
#include <cstddef>

#define BSZ   65536
#define DD    256
#define CC    128
#define HH    1024
#define NSPLIT 128

// ---------------- device-global scratch (no allocation allowed) ----------------
__device__ __nv_bfloat16 g_A0_hi[(size_t)BSZ * 256];
__device__ __nv_bfloat16 g_A0_lo[(size_t)BSZ * 256];
__device__ __nv_bfloat16 g_h1_hi[(size_t)BSZ * HH];
__device__ __nv_bfloat16 g_h1_lo[(size_t)BSZ * HH];
__device__ __nv_bfloat16 g_h2_hi[(size_t)BSZ * HH];
__device__ __nv_bfloat16 g_h2_lo[(size_t)BSZ * HH];
__device__ __nv_bfloat16 g_W1t_hi[1024 * 256];   // [N=1024][K=256]
__device__ __nv_bfloat16 g_W1t_lo[1024 * 256];
__device__ __nv_bfloat16 g_W2t_hi[1024 * 1024];  // [N=1024][K=1024]
__device__ __nv_bfloat16 g_W2t_lo[1024 * 1024];
__device__ __nv_bfloat16 g_Wst_hi[256 * 1024];   // [N=256 interleaved S|T][K=1024]
__device__ __nv_bfloat16 g_Wst_lo[256 * 1024];

// ---------------- PTX helpers ----------------
__device__ __forceinline__ unsigned smem_u32(const void* p) {
    return (unsigned)__cvta_generic_to_shared(p);
}
__device__ __forceinline__ void cp16(unsigned dst, const void* src) {
    asm volatile("cp.async.cg.shared.global [%0], [%1], 16;\n" :: "r"(dst), "l"(src));
}
__device__ __forceinline__ void cp_commit() { asm volatile("cp.async.commit_group;\n"); }
__device__ __forceinline__ void cp_wait0()  { asm volatile("cp.async.wait_group 0;\n"); }

__device__ __forceinline__ void ldsm4(uint32_t& r0, uint32_t& r1, uint32_t& r2, uint32_t& r3,
                                      unsigned addr) {
    asm volatile("ldmatrix.sync.aligned.m8n8.x4.shared.b16 {%0,%1,%2,%3}, [%4];\n"
                 : "=r"(r0), "=r"(r1), "=r"(r2), "=r"(r3) : "r"(addr));
}

__device__ __forceinline__ void mma_bf16(float& c0, float& c1, float& c2, float& c3,
                                         uint32_t a0, uint32_t a1, uint32_t a2, uint32_t a3,
                                         uint32_t b0, uint32_t b1) {
    asm volatile(
        "mma.sync.aligned.m16n8k16.row.col.f32.bf16.bf16.f32 "
        "{%0,%1,%2,%3},{%4,%5,%6,%7},{%8,%9},{%0,%1,%2,%3};\n"
        : "+f"(c0), "+f"(c1), "+f"(c2), "+f"(c3)
        : "r"(a0), "r"(a1), "r"(a2), "r"(a3), "r"(b0), "r"(b1));
}

__device__ __forceinline__ void split2(float a, float b, uint32_t& hi, uint32_t& lo) {
    __nv_bfloat16 ha = __float2bfloat16_rn(a);
    __nv_bfloat16 hb = __float2bfloat16_rn(b);
    __nv_bfloat16 la = __float2bfloat16_rn(a - __bfloat162float(ha));
    __nv_bfloat16 lb = __float2bfloat16_rn(b - __bfloat162float(hb));
    hi = (uint32_t)__bfloat16_as_ushort(ha) | ((uint32_t)__bfloat16_as_ushort(hb) << 16);
    lo = (uint32_t)__bfloat16_as_ushort(la) | ((uint32_t)__bfloat16_as_ushort(lb) << 16);
}

// ---------------- merged pre-pass kernel ----------------
__global__ void prepass_kernel(const float* __restrict__ x, const float* __restrict__ cond,
                               const float* __restrict__ W1, const float* __restrict__ W2,
                               const float* __restrict__ Ws, const float* __restrict__ Wt) {
    const int b = blockIdx.x;
    const int tid = threadIdx.x;
    if (b < 65536) {
        size_t idx = (size_t)b * 256 + tid;
        int col = (int)(idx & 255);
        size_t row = idx >> 8;
        float v = (col < 128) ? x[row * DD + 2 * col] : cond[row * CC + (col - 128)];
        __nv_bfloat16 h = __float2bfloat16_rn(v);
        g_A0_hi[idx] = h;
        g_A0_lo[idx] = __float2bfloat16_rn(v - __bfloat162float(h));
    } else if (b < 66560) {
        size_t idx = (size_t)(b - 65536) * 256 + tid;    // over 1024*256
        int k = (int)(idx & 255);
        size_t n = idx >> 8;
        float v = W1[(size_t)k * 1024 + n];
        __nv_bfloat16 h = __float2bfloat16_rn(v);
        g_W1t_hi[idx] = h;
        g_W1t_lo[idx] = __float2bfloat16_rn(v - __bfloat162float(h));
    } else if (b < 70656) {
        size_t idx = (size_t)(b - 66560) * 256 + tid;    // over 1024*1024
        int k = (int)(idx & 1023);
        size_t n = idx >> 10;
        float v = W2[(size_t)k * 1024 + n];
        __nv_bfloat16 h = __float2bfloat16_rn(v);
        g_W2t_hi[idx] = h;
        g_W2t_lo[idx] = __float2bfloat16_rn(v - __bfloat162float(h));
    } else {
        size_t idx = (size_t)(b - 70656) * 256 + tid;    // over 256*1024
        int k = (int)(idx & 1023);
        int n = (int)(idx >> 10);
        const float* W = (n & 1) ? Wt : Ws;
        float v = W[(size_t)k * NSPLIT + (n >> 1)];
        __nv_bfloat16 h = __float2bfloat16_rn(v);
        g_Wst_hi[idx] = h;
        g_Wst_lo[idx] = __float2bfloat16_rn(v - __bfloat162float(h));
    }
}

// term-major MMA emission for one nfp group: pass1 = ah*bh over all 4
// positions, pass2 = ah*bl, pass3 = al*bh. Per-accumulator order stays
// hh -> hl -> lh (bit-identical to the position-major version), but
// same-accumulator reuse distance is 4 MMAs instead of 1.
#define MMA_GROUP(c, ah, al, bh, bl, nfp)                                            \
    do {                                                                             \
        mma_bf16(c[0][(nfp)*2+0][0], c[0][(nfp)*2+0][1], c[0][(nfp)*2+0][2],         \
                 c[0][(nfp)*2+0][3], ah[0][0], ah[0][1], ah[0][2], ah[0][3],         \
                 bh[0], bh[1]);                                                      \
        mma_bf16(c[1][(nfp)*2+0][0], c[1][(nfp)*2+0][1], c[1][(nfp)*2+0][2],         \
                 c[1][(nfp)*2+0][3], ah[1][0], ah[1][1], ah[1][2], ah[1][3],         \
                 bh[0], bh[1]);                                                      \
        mma_bf16(c[0][(nfp)*2+1][0], c[0][(nfp)*2+1][1], c[0][(nfp)*2+1][2],         \
                 c[0][(nfp)*2+1][3], ah[0][0], ah[0][1], ah[0][2], ah[0][3],         \
                 bh[2], bh[3]);                                                      \
        mma_bf16(c[1][(nfp)*2+1][0], c[1][(nfp)*2+1][1], c[1][(nfp)*2+1][2],         \
                 c[1][(nfp)*2+1][3], ah[1][0], ah[1][1], ah[1][2], ah[1][3],         \
                 bh[2], bh[3]);                                                      \
        mma_bf16(c[0][(nfp)*2+0][0], c[0][(nfp)*2+0][1], c[0][(nfp)*2+0][2],         \
                 c[0][(nfp)*2+0][3], ah[0][0], ah[0][1], ah[0][2], ah[0][3],         \
                 bl[0], bl[1]);                                                      \
        mma_bf16(c[1][(nfp)*2+0][0], c[1][(nfp)*2+0][1], c[1][(nfp)*2+0][2],         \
                 c[1][(nfp)*2+0][3], ah[1][0], ah[1][1], ah[1][2], ah[1][3],         \
                 bl[0], bl[1]);                                                      \
        mma_bf16(c[0][(nfp)*2+1][0], c[0][(nfp)*2+1][1], c[0][(nfp)*2+1][2],         \
                 c[0][(nfp)*2+1][3], ah[0][0], ah[0][1], ah[0][2], ah[0][3],         \
                 bl[2], bl[3]);                                                      \
        mma_bf16(c[1][(nfp)*2+1][0], c[1][(nfp)*2+1][1], c[1][(nfp)*2+1][2],         \
                 c[1][(nfp)*2+1][3], ah[1][0], ah[1][1], ah[1][2], ah[1][3],         \
                 bl[2], bl[3]);                                                      \
        mma_bf16(c[0][(nfp)*2+0][0], c[0][(nfp)*2+0][1], c[0][(nfp)*2+0][2],         \
                 c[0][(nfp)*2+0][3], al[0][0], al[0][1], al[0][2], al[0][3],         \
                 bh[0], bh[1]);                                                      \
        mma_bf16(c[1][(nfp)*2+0][0], c[1][(nfp)*2+0][1], c[1][(nfp)*2+0][2],         \
                 c[1][(nfp)*2+0][3], al[1][0], al[1][1], al[1][2], al[1][3],         \
                 bh[0], bh[1]);                                                      \
        mma_bf16(c[0][(nfp)*2+1][0], c[0][(nfp)*2+1][1], c[0][(nfp)*2+1][2],         \
                 c[0][(nfp)*2+1][3], al[0][0], al[0][1], al[0][2], al[0][3],         \
                 bh[2], bh[3]);                                                      \
        mma_bf16(c[1][(nfp)*2+1][0], c[1][(nfp)*2+1][1], c[1][(nfp)*2+1][2],         \
                 c[1][(nfp)*2+1][3], al[1][0], al[1][1], al[1][2], al[1][3],         \
                 bh[2], bh[3]);                                                      \
    } while (0)

// =====================================================================
// GEMM1/2: C = relu(A @ Bt^T + bias). CTA 128x128, 8 warps (32x64 tiles).
// =====================================================================
template <int K, int MODE>
__global__ void __launch_bounds__(256, 2)
gemm12_kernel(const float* __restrict__ bias) {
    constexpr int BM = 128, BN = 128, BK = 32;
    constexpr int LD = 40;                        // halves per smem row (80B)
    constexpr int NK = K / BK;
    constexpr int TILE_A = BM * LD;               // 5120 halves
    constexpr int TILE_B = BN * LD;               // 5120 halves
    constexpr int STAGE = 2 * TILE_A + 2 * TILE_B;

    extern __shared__ __nv_bfloat16 sm[];
    const unsigned sbase = smem_u32(sm);

    const int tid = threadIdx.x;
    const int bx = blockIdx.x, by = blockIdx.y;
    const int warp = tid >> 5, lane = tid & 31;
    const int wm = warp & 3, wn = warp >> 2;      // 4x2 warps: warp tile 32x64
    const int g = lane >> 2, tg = lane & 3;

    const __nv_bfloat16* Ahi = MODE ? g_h1_hi : g_A0_hi;
    const __nv_bfloat16* Alo = MODE ? g_h1_lo : g_A0_lo;
    const __nv_bfloat16* Bhi = MODE ? g_W2t_hi : g_W1t_hi;
    const __nv_bfloat16* Blo = MODE ? g_W2t_lo : g_W1t_lo;

    float c[2][8][4];
#pragma unroll
    for (int mf = 0; mf < 2; mf++)
#pragma unroll
        for (int nf = 0; nf < 8; nf++)
#pragma unroll
            for (int r = 0; r < 4; r++) c[mf][nf][r] = 0.f;

    // ldmatrix per-lane offsets (bytes)
    const int arow = (lane & 7) + ((lane >> 3) & 1) * 8;
    const int akk  = (lane >> 4) * 8;
    unsigned aoff[2];
#pragma unroll
    for (int mf = 0; mf < 2; mf++)
        aoff[mf] = (unsigned)(((wm * 32 + mf * 16 + arow) * LD + akk) * 2);
    const int brow = (lane & 7) + (lane >> 4) * 8;
    const int bkk  = ((lane >> 3) & 1) * 8;
    unsigned boff[4];
#pragma unroll
    for (int nfp = 0; nfp < 4; nfp++)
        boff[nfp] = (unsigned)(((wn * 64 + nfp * 16 + brow) * LD + bkk) * 2);

    auto load_tile = [&](int kt, int st) {
        __nv_bfloat16* base = sm + st * STAGE;
#pragma unroll
        for (int l = 0; l < 2; l++) {
            int e = l * 256 + tid;
            int r = e >> 2, cc = (e & 3) * 8;
            size_t ga = (size_t)(by * BM + r) * K + kt * BK + cc;
            size_t gb = (size_t)(bx * BN + r) * K + kt * BK + cc;
            unsigned so = (unsigned)(r * LD + cc);
            cp16(smem_u32(base + so), Ahi + ga);
            cp16(smem_u32(base + TILE_A + so), Alo + ga);
            cp16(smem_u32(base + 2 * TILE_A + so), Bhi + gb);
            cp16(smem_u32(base + 2 * TILE_A + TILE_B + so), Blo + gb);
        }
    };

    load_tile(0, 0);
    cp_commit();

    for (int kt = 0; kt < NK; kt++) {
        cp_wait0();
        __syncthreads();
        if (kt + 1 < NK) { load_tile(kt + 1, (kt + 1) & 1); cp_commit(); }

        const unsigned stb = sbase + (unsigned)((kt & 1) * STAGE * 2);
#pragma unroll
        for (int ks = 0; ks < 2; ks++) {
            const unsigned k0b = (unsigned)(ks * 16 * 2);
            uint32_t ah[2][4], al[2][4];
#pragma unroll
            for (int mf = 0; mf < 2; mf++) {
                ldsm4(ah[mf][0], ah[mf][1], ah[mf][2], ah[mf][3], stb + aoff[mf] + k0b);
                ldsm4(al[mf][0], al[mf][1], al[mf][2], al[mf][3],
                      stb + (unsigned)(TILE_A * 2) + aoff[mf] + k0b);
            }
#pragma unroll
            for (int nfp = 0; nfp < 4; nfp++) {
                uint32_t bh[4], bl[4];
                ldsm4(bh[0], bh[1], bh[2], bh[3],
                      stb + (unsigned)(2 * TILE_A * 2) + boff[nfp] + k0b);
                ldsm4(bl[0], bl[1], bl[2], bl[3],
                      stb + (unsigned)((2 * TILE_A + TILE_B) * 2) + boff[nfp] + k0b);
                MMA_GROUP(c, ah, al, bh, bl, nfp);
            }
        }
    }

    // epilogue: bias + relu, store split bf16
    __nv_bfloat16* Ohi = MODE ? g_h2_hi : g_h1_hi;
    __nv_bfloat16* Olo = MODE ? g_h2_lo : g_h1_lo;
#pragma unroll
    for (int mf = 0; mf < 2; mf++) {
        int r0 = by * BM + wm * 32 + mf * 16 + g;
#pragma unroll
        for (int nf = 0; nf < 8; nf++) {
            int nc = bx * BN + wn * 64 + nf * 8 + 2 * tg;
            float2 bv = *(const float2*)&bias[nc];
            float v0 = fmaxf(c[mf][nf][0] + bv.x, 0.f);
            float v1 = fmaxf(c[mf][nf][1] + bv.y, 0.f);
            float v2 = fmaxf(c[mf][nf][2] + bv.x, 0.f);
            float v3 = fmaxf(c[mf][nf][3] + bv.y, 0.f);
            uint32_t hi, lo;
            size_t o0 = (size_t)r0 * HH + nc;
            split2(v0, v1, hi, lo);
            *(uint32_t*)(Ohi + o0) = hi;
            *(uint32_t*)(Olo + o0) = lo;
            size_t o1 = (size_t)(r0 + 8) * HH + nc;
            split2(v2, v3, hi, lo);
            *(uint32_t*)(Ohi + o1) = hi;
            *(uint32_t*)(Olo + o1) = lo;
        }
    }
}

// =====================================================================
// GEMM3: [S|T] = h2 @ Wst^T; coupling + logdet. CTA 64x256, 8 warps (2x4).
// =====================================================================
__global__ void __launch_bounds__(256, 2)
final_kernel(const float* __restrict__ bs, const float* __restrict__ bt,
             const float* __restrict__ x, float* __restrict__ out,
             float* __restrict__ logdet) {
    constexpr int BM = 64, BN = 256, BK = 32;
    constexpr int LD = 40;
    constexpr int K = HH, NK = K / BK;
    constexpr int TILE_A = BM * LD;               // 2560 halves
    constexpr int TILE_B = BN * LD;               // 10240 halves
    constexpr int STAGE = 2 * TILE_A + 2 * TILE_B;

    extern __shared__ __nv_bfloat16 sm[];
    float* sdet = (float*)(sm + 2 * STAGE);       // 64 floats
    const unsigned sbase = smem_u32(sm);

    const int tid = threadIdx.x;
    const int by = blockIdx.x;
    const int warp = tid >> 5, lane = tid & 31;
    const int wm = warp & 1, wn = warp >> 1;      // 2x4 warps, warp tile 32x64
    const int g = lane >> 2, tg = lane & 3;

    if (tid < 64) sdet[tid] = 0.f;

    float c[2][8][4];
#pragma unroll
    for (int mf = 0; mf < 2; mf++)
#pragma unroll
        for (int nf = 0; nf < 8; nf++)
#pragma unroll
            for (int r = 0; r < 4; r++) c[mf][nf][r] = 0.f;

    const int arow = (lane & 7) + ((lane >> 3) & 1) * 8;
    const int akk  = (lane >> 4) * 8;
    unsigned aoff[2];
#pragma unroll
    for (int mf = 0; mf < 2; mf++)
        aoff[mf] = (unsigned)(((wm * 32 + mf * 16 + arow) * LD + akk) * 2);
    const int brow = (lane & 7) + (lane >> 4) * 8;
    const int bkk  = ((lane >> 3) & 1) * 8;
    unsigned boff[4];
#pragma unroll
    for (int nfp = 0; nfp < 4; nfp++)
        boff[nfp] = (unsigned)(((wn * 64 + nfp * 16 + brow) * LD + bkk) * 2);

    auto load_tile = [&](int kt, int st) {
        __nv_bfloat16* base = sm + st * STAGE;
        // A: 64 rows x 32 halves = 256 chunks
        {
            int r = tid >> 2, cc = (tid & 3) * 8;
            size_t goff = (size_t)(by * BM + r) * K + kt * BK + cc;
            cp16(smem_u32(base + r * LD + cc), g_h2_hi + goff);
            cp16(smem_u32(base + TILE_A + r * LD + cc), g_h2_lo + goff);
        }
        // B: 256 rows x 32 halves = 1024 chunks
#pragma unroll
        for (int l = 0; l < 4; l++) {
            int e = l * 256 + tid;
            int r = e >> 2, cc = (e & 3) * 8;
            size_t goff = (size_t)r * K + kt * BK + cc;
            cp16(smem_u32(base + 2 * TILE_A + r * LD + cc), g_Wst_hi + goff);
            cp16(smem_u32(base + 2 * TILE_A + TILE_B + r * LD + cc), g_Wst_lo + goff);
        }
    };

    load_tile(0, 0);
    cp_commit();

    for (int kt = 0; kt < NK; kt++) {
        cp_wait0();
        __syncthreads();
        if (kt + 1 < NK) { load_tile(kt + 1, (kt + 1) & 1); cp_commit(); }

        const unsigned stb = sbase + (unsigned)((kt & 1) * STAGE * 2);
#pragma unroll
        for (int ks = 0; ks < 2; ks++) {
            const unsigned k0b = (unsigned)(ks * 16 * 2);
            uint32_t ah[2][4], al[2][4];
#pragma unroll
            for (int mf = 0; mf < 2; mf++) {
                ldsm4(ah[mf][0], ah[mf][1], ah[mf][2], ah[mf][3], stb + aoff[mf] + k0b);
                ldsm4(al[mf][0], al[mf][1], al[mf][2], al[mf][3],
                      stb + (unsigned)(TILE_A * 2) + aoff[mf] + k0b);
            }
#pragma unroll
            for (int nfp = 0; nfp < 4; nfp++) {
                uint32_t bh[4], bl[4];
                ldsm4(bh[0], bh[1], bh[2], bh[3],
                      stb + (unsigned)(2 * TILE_A * 2) + boff[nfp] + k0b);
                ldsm4(bl[0], bl[1], bl[2], bl[3],
                      stb + (unsigned)((2 * TILE_A + TILE_B) * 2) + boff[nfp] + k0b);
                MMA_GROUP(c, ah, al, bh, bl, nfp);
            }
        }
    }

    // coupling epilogue: even col = S, odd col = T (interleaved Wst)
#pragma unroll
    for (int mf = 0; mf < 2; mf++) {
        int lr = wm * 32 + mf * 16 + g;
        size_t r0 = (size_t)(by * BM + lr);
        float ld0 = 0.f, ld1 = 0.f;
#pragma unroll
        for (int nf = 0; nf < 8; nf++) {
            int nc = wn * 64 + nf * 8 + 2 * tg;   // even col in [0,256)
            int j = nc >> 1;                      // pair index in [0,128)
            float bsv = __ldg(&bs[j]);
            float btv = __ldg(&bt[j]);

            float ls0 = tanhf(c[mf][nf][0] + bsv);
            float t0  = c[mf][nf][1] + btv;
            float2 xv0 = *(const float2*)&x[r0 * DD + 2 * j];
            *(float2*)&out[r0 * DD + 2 * j] =
                make_float2(xv0.x, xv0.y * expf(ls0) + t0);
            ld0 += ls0;

            float ls1 = tanhf(c[mf][nf][2] + bsv);
            float t1  = c[mf][nf][3] + btv;
            float2 xv1 = *(const float2*)&x[(r0 + 8) * DD + 2 * j];
            *(float2*)&out[(r0 + 8) * DD + 2 * j] =
                make_float2(xv1.x, xv1.y * expf(ls1) + t1);
            ld1 += ls1;
        }
        atomicAdd(&sdet[lr], ld0);
        atomicAdd(&sdet[lr + 8], ld1);
    }
    __syncthreads();
    if (tid < 64) logdet[(size_t)by * BM + tid] = sdet[tid];
}

// ---------------- launch ----------------
extern "C" void kernel_launch(void* const* d_in, const int* in_sizes, int n_in,
                              void* d_out, int out_size) {
    const float* x    = (const float*)d_in[0];
    const float* cond = (const float*)d_in[1];
    const float* W1   = (const float*)d_in[2];
    const float* b1   = (const float*)d_in[3];
    const float* W2   = (const float*)d_in[4];
    const float* b2   = (const float*)d_in[5];
    const float* Ws   = (const float*)d_in[6];
    const float* bs   = (const float*)d_in[7];
    const float* Wt   = (const float*)d_in[8];
    const float* bt   = (const float*)d_in[9];

    float* out = (float*)d_out;
    float* logdet = out + ((size_t)out_size - BSZ);

    const int gemm_smem  = 2 * (2 * 128 * 40 + 2 * 128 * 40) * 2;            // 81920
    const int final_smem = 2 * (2 * 64 * 40 + 2 * 256 * 40) * 2 + 64 * 4;    // 102656

    cudaFuncSetAttribute(gemm12_kernel<256, 0>,
                         cudaFuncAttributeMaxDynamicSharedMemorySize, gemm_smem);
    cudaFuncSetAttribute(gemm12_kernel<1024, 1>,
                         cudaFuncAttributeMaxDynamicSharedMemorySize, gemm_smem);
    cudaFuncSetAttribute(final_kernel,
                         cudaFuncAttributeMaxDynamicSharedMemorySize, final_smem);

    // merged pre-pass: split/transpose all operands (71680 blocks)
    prepass_kernel<<<71680, 256>>>(x, cond, W1, W2, Ws, Wt);

    // h1 = relu([x_even|cond] @ W1 + b1)
    gemm12_kernel<256, 0><<<dim3(8, BSZ / 128), 256, gemm_smem>>>(b1);
    // h2 = relu(h1 @ W2 + b2)
    gemm12_kernel<1024, 1><<<dim3(8, BSZ / 128), 256, gemm_smem>>>(b2);
    // S/T + coupling + logdet
    final_kernel<<<BSZ / 64, 256, final_smem>>>(bs, bt, x, out, logdet);
}

// round 14
// speedup vs baseline: 1.0952x; 1.0952x over previous
#include <cuda_runtime.h>
#include <cuda_bf16.h>
#include <cstdint>
#include <cstddef>

#define BSZ   65536
#define DD    256
#define CC    128
#define HH    1024
#define NSPLIT 128

// ---------------- device-global scratch (no allocation allowed) ----------------
__device__ __nv_bfloat16 g_A0_hi[(size_t)BSZ * 256];
__device__ __nv_bfloat16 g_A0_lo[(size_t)BSZ * 256];
__device__ __nv_bfloat16 g_h1_hi[(size_t)BSZ * HH];
__device__ __nv_bfloat16 g_h1_lo[(size_t)BSZ * HH];
__device__ __nv_bfloat16 g_h2_hi[(size_t)BSZ * HH];
__device__ __nv_bfloat16 g_h2_lo[(size_t)BSZ * HH];
__device__ __nv_bfloat16 g_W1t_hi[1024 * 256];   // [N=1024][K=256]
__device__ __nv_bfloat16 g_W1t_lo[1024 * 256];
__device__ __nv_bfloat16 g_W2t_hi[1024 * 1024];  // [N=1024][K=1024]
__device__ __nv_bfloat16 g_W2t_lo[1024 * 1024];
__device__ __nv_bfloat16 g_Wst_hi[256 * 1024];   // [N=256 interleaved S|T][K=1024]
__device__ __nv_bfloat16 g_Wst_lo[256 * 1024];

// ---------------- PTX helpers ----------------
__device__ __forceinline__ unsigned smem_u32(const void* p) {
    return (unsigned)__cvta_generic_to_shared(p);
}
__device__ __forceinline__ void cp16(unsigned dst, const void* src) {
    asm volatile("cp.async.cg.shared.global [%0], [%1], 16;\n" :: "r"(dst), "l"(src));
}
__device__ __forceinline__ void cp_commit() { asm volatile("cp.async.commit_group;\n"); }
__device__ __forceinline__ void cp_wait0()  { asm volatile("cp.async.wait_group 0;\n"); }
__device__ __forceinline__ void cp_wait1()  { asm volatile("cp.async.wait_group 1;\n"); }

__device__ __forceinline__ void ldsm4(uint32_t& r0, uint32_t& r1, uint32_t& r2, uint32_t& r3,
                                      unsigned addr) {
    asm volatile("ldmatrix.sync.aligned.m8n8.x4.shared.b16 {%0,%1,%2,%3}, [%4];\n"
                 : "=r"(r0), "=r"(r1), "=r"(r2), "=r"(r3) : "r"(addr));
}

__device__ __forceinline__ void mma_bf16(float& c0, float& c1, float& c2, float& c3,
                                         uint32_t a0, uint32_t a1, uint32_t a2, uint32_t a3,
                                         uint32_t b0, uint32_t b1) {
    asm volatile(
        "mma.sync.aligned.m16n8k16.row.col.f32.bf16.bf16.f32 "
        "{%0,%1,%2,%3},{%4,%5,%6,%7},{%8,%9},{%0,%1,%2,%3};\n"
        : "+f"(c0), "+f"(c1), "+f"(c2), "+f"(c3)
        : "r"(a0), "r"(a1), "r"(a2), "r"(a3), "r"(b0), "r"(b1));
}

__device__ __forceinline__ void split2(float a, float b, uint32_t& hi, uint32_t& lo) {
    __nv_bfloat16 ha = __float2bfloat16_rn(a);
    __nv_bfloat16 hb = __float2bfloat16_rn(b);
    __nv_bfloat16 la = __float2bfloat16_rn(a - __bfloat162float(ha));
    __nv_bfloat16 lb = __float2bfloat16_rn(b - __bfloat162float(hb));
    hi = (uint32_t)__bfloat16_as_ushort(ha) | ((uint32_t)__bfloat16_as_ushort(hb) << 16);
    lo = (uint32_t)__bfloat16_as_ushort(la) | ((uint32_t)__bfloat16_as_ushort(lb) << 16);
}

// ---------------- merged pre-pass kernel ----------------
__global__ void prepass_kernel(const float* __restrict__ x, const float* __restrict__ cond,
                               const float* __restrict__ W1, const float* __restrict__ W2,
                               const float* __restrict__ Ws, const float* __restrict__ Wt) {
    const int b = blockIdx.x;
    const int tid = threadIdx.x;
    if (b < 65536) {
        size_t idx = (size_t)b * 256 + tid;
        int col = (int)(idx & 255);
        size_t row = idx >> 8;
        float v = (col < 128) ? x[row * DD + 2 * col] : cond[row * CC + (col - 128)];
        __nv_bfloat16 h = __float2bfloat16_rn(v);
        g_A0_hi[idx] = h;
        g_A0_lo[idx] = __float2bfloat16_rn(v - __bfloat162float(h));
    } else if (b < 66560) {
        size_t idx = (size_t)(b - 65536) * 256 + tid;    // over 1024*256
        int k = (int)(idx & 255);
        size_t n = idx >> 8;
        float v = W1[(size_t)k * 1024 + n];
        __nv_bfloat16 h = __float2bfloat16_rn(v);
        g_W1t_hi[idx] = h;
        g_W1t_lo[idx] = __float2bfloat16_rn(v - __bfloat162float(h));
    } else if (b < 70656) {
        size_t idx = (size_t)(b - 66560) * 256 + tid;    // over 1024*1024
        int k = (int)(idx & 1023);
        size_t n = idx >> 10;
        float v = W2[(size_t)k * 1024 + n];
        __nv_bfloat16 h = __float2bfloat16_rn(v);
        g_W2t_hi[idx] = h;
        g_W2t_lo[idx] = __float2bfloat16_rn(v - __bfloat162float(h));
    } else {
        size_t idx = (size_t)(b - 70656) * 256 + tid;    // over 256*1024
        int k = (int)(idx & 1023);
        int n = (int)(idx >> 10);
        const float* W = (n & 1) ? Wt : Ws;
        float v = W[(size_t)k * NSPLIT + (n >> 1)];
        __nv_bfloat16 h = __float2bfloat16_rn(v);
        g_Wst_hi[idx] = h;
        g_Wst_lo[idx] = __float2bfloat16_rn(v - __bfloat162float(h));
    }
}

// =====================================================================
// GEMM1/2: C = relu(A @ Bt^T + bias). CTA 128x128, 8 warps (32x64 tiles).
// 3-stage cp.async ring, prefetch distance 2 (wait_group 1).
// Unpadded 64B rows with XOR swizzle: 16B chunk c stored at c ^ ((row>>1)&3).
// All smem chunk addresses are 16B-aligned; ldmatrix phases conflict-free.
// MODE 0: h1 = relu(A0 @ W1t^T + b1), K=256
// MODE 1: h2 = relu(h1 @ W2t^T + b2), K=1024
// =====================================================================
template <int K, int MODE>
__global__ void __launch_bounds__(256, 2)
gemm12_kernel(const float* __restrict__ bias) {
    constexpr int BM = 128, BN = 128, BK = 32;
    constexpr int NK = K / BK;
    constexpr int TILE_BYTES  = BM * 64;          // 8192 B (one operand tile)
    constexpr int STAGE_BYTES = 4 * TILE_BYTES;   // Ah Al Bh Bl = 32768 B

    extern __shared__ __nv_bfloat16 sm[];
    const unsigned sbase = smem_u32(sm);

    const int tid = threadIdx.x;
    const int bx = blockIdx.x, by = blockIdx.y;
    const int warp = tid >> 5, lane = tid & 31;
    const int wm = warp & 3, wn = warp >> 2;      // 4x2 warps: warp tile 32x64
    const int g = lane >> 2, tg = lane & 3;

    const __nv_bfloat16* Ahi = MODE ? g_h1_hi : g_A0_hi;
    const __nv_bfloat16* Alo = MODE ? g_h1_lo : g_A0_lo;
    const __nv_bfloat16* Bhi = MODE ? g_W2t_hi : g_W1t_hi;
    const __nv_bfloat16* Blo = MODE ? g_W2t_lo : g_W1t_lo;

    float c[2][8][4];
#pragma unroll
    for (int mf = 0; mf < 2; mf++)
#pragma unroll
        for (int nf = 0; nf < 8; nf++)
#pragma unroll
            for (int r = 0; r < 4; r++) c[mf][nf][r] = 0.f;

    // ldmatrix per-lane row/chunk decomposition
    const int arow = (lane & 7) + ((lane >> 3) & 1) * 8;  // row within 16
    const int acb  = lane >> 4;                           // chunk base 0..1
    const int brow = (lane & 7) + (lane >> 4) * 8;
    const int bcb  = (lane >> 3) & 1;
    int aRowB[2], aSw[2];
#pragma unroll
    for (int mf = 0; mf < 2; mf++) {
        int row = wm * 32 + mf * 16 + arow;
        aRowB[mf] = row * 64;
        aSw[mf] = (row >> 1) & 3;
    }
    int bRowB[4], bSw[4];
#pragma unroll
    for (int nfp = 0; nfp < 4; nfp++) {
        int row = wn * 64 + nfp * 16 + brow;
        bRowB[nfp] = row * 64;
        bSw[nfp] = (row >> 1) & 3;
    }

    auto load_tile = [&](int kt, int st) {
        const unsigned base = sbase + (unsigned)(st * STAGE_BYTES);
#pragma unroll
        for (int l = 0; l < 2; l++) {
            int e = l * 256 + tid;
            int r = e >> 2, ch = e & 3;
            int swc = ch ^ ((r >> 1) & 3);
            unsigned so = (unsigned)(r * 64 + swc * 16);
            size_t ga = (size_t)(by * BM + r) * K + kt * BK + ch * 8;
            size_t gb = (size_t)(bx * BN + r) * K + kt * BK + ch * 8;
            cp16(base + so, Ahi + ga);
            cp16(base + TILE_BYTES + so, Alo + ga);
            cp16(base + 2 * TILE_BYTES + so, Bhi + gb);
            cp16(base + 3 * TILE_BYTES + so, Blo + gb);
        }
    };

    load_tile(0, 0);
    cp_commit();
    load_tile(1, 1);
    cp_commit();

    int smain = 0, sload = 2;
    for (int kt = 0; kt < NK; kt++) {
        cp_wait1();            // tile kt landed; tile kt+1 may still be in flight
        __syncthreads();       // buffer sload (tile kt-1) fully consumed
        if (kt + 2 < NK) load_tile(kt + 2, sload);
        cp_commit();           // unconditional: group-count semantics in tail

        const unsigned stb = sbase + (unsigned)(smain * STAGE_BYTES);
#pragma unroll
        for (int ks = 0; ks < 2; ks++) {
            uint32_t ah[2][4], al[2][4];
#pragma unroll
            for (int mf = 0; mf < 2; mf++) {
                unsigned ach = (unsigned)(((ks * 2 + acb) ^ aSw[mf]) << 4);
                ldsm4(ah[mf][0], ah[mf][1], ah[mf][2], ah[mf][3],
                      stb + (unsigned)aRowB[mf] + ach);
                ldsm4(al[mf][0], al[mf][1], al[mf][2], al[mf][3],
                      stb + (unsigned)TILE_BYTES + (unsigned)aRowB[mf] + ach);
            }
#pragma unroll
            for (int nfp = 0; nfp < 4; nfp++) {
                unsigned bch = (unsigned)(((ks * 2 + bcb) ^ bSw[nfp]) << 4);
                uint32_t bh[4], bl[4];
                ldsm4(bh[0], bh[1], bh[2], bh[3],
                      stb + (unsigned)(2 * TILE_BYTES) + (unsigned)bRowB[nfp] + bch);
                ldsm4(bl[0], bl[1], bl[2], bl[3],
                      stb + (unsigned)(3 * TILE_BYTES) + (unsigned)bRowB[nfp] + bch);
#pragma unroll
                for (int sub = 0; sub < 2; sub++) {
                    int nf = nfp * 2 + sub;
#pragma unroll
                    for (int mf = 0; mf < 2; mf++) {
                        mma_bf16(c[mf][nf][0], c[mf][nf][1], c[mf][nf][2], c[mf][nf][3],
                                 ah[mf][0], ah[mf][1], ah[mf][2], ah[mf][3],
                                 bh[2 * sub], bh[2 * sub + 1]);
                        mma_bf16(c[mf][nf][0], c[mf][nf][1], c[mf][nf][2], c[mf][nf][3],
                                 ah[mf][0], ah[mf][1], ah[mf][2], ah[mf][3],
                                 bl[2 * sub], bl[2 * sub + 1]);
                        mma_bf16(c[mf][nf][0], c[mf][nf][1], c[mf][nf][2], c[mf][nf][3],
                                 al[mf][0], al[mf][1], al[mf][2], al[mf][3],
                                 bh[2 * sub], bh[2 * sub + 1]);
                    }
                }
            }
        }
        smain = (smain == 2) ? 0 : smain + 1;
        sload = (sload == 2) ? 0 : sload + 1;
    }

    // epilogue: bias + relu, store split bf16
    __nv_bfloat16* Ohi = MODE ? g_h2_hi : g_h1_hi;
    __nv_bfloat16* Olo = MODE ? g_h2_lo : g_h1_lo;
#pragma unroll
    for (int mf = 0; mf < 2; mf++) {
        int r0 = by * BM + wm * 32 + mf * 16 + g;
#pragma unroll
        for (int nf = 0; nf < 8; nf++) {
            int nc = bx * BN + wn * 64 + nf * 8 + 2 * tg;
            float2 bv = *(const float2*)&bias[nc];
            float v0 = fmaxf(c[mf][nf][0] + bv.x, 0.f);
            float v1 = fmaxf(c[mf][nf][1] + bv.y, 0.f);
            float v2 = fmaxf(c[mf][nf][2] + bv.x, 0.f);
            float v3 = fmaxf(c[mf][nf][3] + bv.y, 0.f);
            uint32_t hi, lo;
            size_t o0 = (size_t)r0 * HH + nc;
            split2(v0, v1, hi, lo);
            *(uint32_t*)(Ohi + o0) = hi;
            *(uint32_t*)(Olo + o0) = lo;
            size_t o1 = (size_t)(r0 + 8) * HH + nc;
            split2(v2, v3, hi, lo);
            *(uint32_t*)(Ohi + o1) = hi;
            *(uint32_t*)(Olo + o1) = lo;
        }
    }
}

// =====================================================================
// GEMM3: [S|T] = h2 @ Wst^T; coupling + logdet. CTA 64x256, 8 warps (2x4).
// (byte-identical to the 1693us version; experiment control)
// =====================================================================
__global__ void __launch_bounds__(256, 2)
final_kernel(const float* __restrict__ bs, const float* __restrict__ bt,
             const float* __restrict__ x, float* __restrict__ out,
             float* __restrict__ logdet) {
    constexpr int BM = 64, BN = 256, BK = 32;
    constexpr int LD = 40;
    constexpr int K = HH, NK = K / BK;
    constexpr int TILE_A = BM * LD;               // 2560 halves
    constexpr int TILE_B = BN * LD;               // 10240 halves
    constexpr int STAGE = 2 * TILE_A + 2 * TILE_B;

    extern __shared__ __nv_bfloat16 sm[];
    float* sdet = (float*)(sm + 2 * STAGE);       // 64 floats
    const unsigned sbase = smem_u32(sm);

    const int tid = threadIdx.x;
    const int by = blockIdx.x;
    const int warp = tid >> 5, lane = tid & 31;
    const int wm = warp & 1, wn = warp >> 1;      // 2x4 warps, warp tile 32x64
    const int g = lane >> 2, tg = lane & 3;

    if (tid < 64) sdet[tid] = 0.f;

    float c[2][8][4];
#pragma unroll
    for (int mf = 0; mf < 2; mf++)
#pragma unroll
        for (int nf = 0; nf < 8; nf++)
#pragma unroll
            for (int r = 0; r < 4; r++) c[mf][nf][r] = 0.f;

    const int arow = (lane & 7) + ((lane >> 3) & 1) * 8;
    const int akk  = (lane >> 4) * 8;
    unsigned aoff[2];
#pragma unroll
    for (int mf = 0; mf < 2; mf++)
        aoff[mf] = (unsigned)(((wm * 32 + mf * 16 + arow) * LD + akk) * 2);
    const int brow = (lane & 7) + (lane >> 4) * 8;
    const int bkk  = ((lane >> 3) & 1) * 8;
    unsigned boff[4];
#pragma unroll
    for (int nfp = 0; nfp < 4; nfp++)
        boff[nfp] = (unsigned)(((wn * 64 + nfp * 16 + brow) * LD + bkk) * 2);

    auto load_tile = [&](int kt, int st) {
        __nv_bfloat16* base = sm + st * STAGE;
        // A: 64 rows x 32 halves = 256 chunks
        {
            int r = tid >> 2, cc = (tid & 3) * 8;
            size_t goff = (size_t)(by * BM + r) * K + kt * BK + cc;
            cp16(smem_u32(base + r * LD + cc), g_h2_hi + goff);
            cp16(smem_u32(base + TILE_A + r * LD + cc), g_h2_lo + goff);
        }
        // B: 256 rows x 32 halves = 1024 chunks
#pragma unroll
        for (int l = 0; l < 4; l++) {
            int e = l * 256 + tid;
            int r = e >> 2, cc = (e & 3) * 8;
            size_t goff = (size_t)r * K + kt * BK + cc;
            cp16(smem_u32(base + 2 * TILE_A + r * LD + cc), g_Wst_hi + goff);
            cp16(smem_u32(base + 2 * TILE_A + TILE_B + r * LD + cc), g_Wst_lo + goff);
        }
    };

    load_tile(0, 0);
    cp_commit();

    for (int kt = 0; kt < NK; kt++) {
        cp_wait0();
        __syncthreads();
        if (kt + 1 < NK) { load_tile(kt + 1, (kt + 1) & 1); cp_commit(); }

        const unsigned stb = sbase + (unsigned)((kt & 1) * STAGE * 2);
#pragma unroll
        for (int ks = 0; ks < 2; ks++) {
            const unsigned k0b = (unsigned)(ks * 16 * 2);
            uint32_t ah[2][4], al[2][4];
#pragma unroll
            for (int mf = 0; mf < 2; mf++) {
                ldsm4(ah[mf][0], ah[mf][1], ah[mf][2], ah[mf][3], stb + aoff[mf] + k0b);
                ldsm4(al[mf][0], al[mf][1], al[mf][2], al[mf][3],
                      stb + (unsigned)(TILE_A * 2) + aoff[mf] + k0b);
            }
#pragma unroll
            for (int nfp = 0; nfp < 4; nfp++) {
                uint32_t bh[4], bl[4];
                ldsm4(bh[0], bh[1], bh[2], bh[3],
                      stb + (unsigned)(2 * TILE_A * 2) + boff[nfp] + k0b);
                ldsm4(bl[0], bl[1], bl[2], bl[3],
                      stb + (unsigned)((2 * TILE_A + TILE_B) * 2) + boff[nfp] + k0b);
#pragma unroll
                for (int sub = 0; sub < 2; sub++) {
                    int nf = nfp * 2 + sub;
#pragma unroll
                    for (int mf = 0; mf < 2; mf++) {
                        mma_bf16(c[mf][nf][0], c[mf][nf][1], c[mf][nf][2], c[mf][nf][3],
                                 ah[mf][0], ah[mf][1], ah[mf][2], ah[mf][3],
                                 bh[2 * sub], bh[2 * sub + 1]);
                        mma_bf16(c[mf][nf][0], c[mf][nf][1], c[mf][nf][2], c[mf][nf][3],
                                 ah[mf][0], ah[mf][1], ah[mf][2], ah[mf][3],
                                 bl[2 * sub], bl[2 * sub + 1]);
                        mma_bf16(c[mf][nf][0], c[mf][nf][1], c[mf][nf][2], c[mf][nf][3],
                                 al[mf][0], al[mf][1], al[mf][2], al[mf][3],
                                 bh[2 * sub], bh[2 * sub + 1]);
                    }
                }
            }
        }
    }

    // coupling epilogue: even col = S, odd col = T (interleaved Wst)
#pragma unroll
    for (int mf = 0; mf < 2; mf++) {
        int lr = wm * 32 + mf * 16 + g;
        size_t r0 = (size_t)(by * BM + lr);
        float ld0 = 0.f, ld1 = 0.f;
#pragma unroll
        for (int nf = 0; nf < 8; nf++) {
            int nc = wn * 64 + nf * 8 + 2 * tg;   // even col in [0,256)
            int j = nc >> 1;                      // pair index in [0,128)
            float bsv = __ldg(&bs[j]);
            float btv = __ldg(&bt[j]);

            float ls0 = tanhf(c[mf][nf][0] + bsv);
            float t0  = c[mf][nf][1] + btv;
            float2 xv0 = *(const float2*)&x[r0 * DD + 2 * j];
            *(float2*)&out[r0 * DD + 2 * j] =
                make_float2(xv0.x, xv0.y * expf(ls0) + t0);
            ld0 += ls0;

            float ls1 = tanhf(c[mf][nf][2] + bsv);
            float t1  = c[mf][nf][3] + btv;
            float2 xv1 = *(const float2*)&x[(r0 + 8) * DD + 2 * j];
            *(float2*)&out[(r0 + 8) * DD + 2 * j] =
                make_float2(xv1.x, xv1.y * expf(ls1) + t1);
            ld1 += ls1;
        }
        atomicAdd(&sdet[lr], ld0);
        atomicAdd(&sdet[lr + 8], ld1);
    }
    __syncthreads();
    if (tid < 64) logdet[(size_t)by * BM + tid] = sdet[tid];
}

// ---------------- launch ----------------
extern "C" void kernel_launch(void* const* d_in, const int* in_sizes, int n_in,
                              void* d_out, int out_size) {
    const float* x    = (const float*)d_in[0];
    const float* cond = (const float*)d_in[1];
    const float* W1   = (const float*)d_in[2];
    const float* b1   = (const float*)d_in[3];
    const float* W2   = (const float*)d_in[4];
    const float* b2   = (const float*)d_in[5];
    const float* Ws   = (const float*)d_in[6];
    const float* bs   = (const float*)d_in[7];
    const float* Wt   = (const float*)d_in[8];
    const float* bt   = (const float*)d_in[9];

    float* out = (float*)d_out;
    float* logdet = out + ((size_t)out_size - BSZ);

    const int gemm_smem  = 3 * 4 * 128 * 64;                                 // 98304
    const int final_smem = 2 * (2 * 64 * 40 + 2 * 256 * 40) * 2 + 64 * 4;    // 102656

    cudaFuncSetAttribute(gemm12_kernel<256, 0>,
                         cudaFuncAttributeMaxDynamicSharedMemorySize, gemm_smem);
    cudaFuncSetAttribute(gemm12_kernel<1024, 1>,
                         cudaFuncAttributeMaxDynamicSharedMemorySize, gemm_smem);
    cudaFuncSetAttribute(final_kernel,
                         cudaFuncAttributeMaxDynamicSharedMemorySize, final_smem);

    // merged pre-pass: split/transpose all operands (71680 blocks)
    prepass_kernel<<<71680, 256>>>(x, cond, W1, W2, Ws, Wt);

    // h1 = relu([x_even|cond] @ W1 + b1)
    gemm12_kernel<256, 0><<<dim3(8, BSZ / 128), 256, gemm_smem>>>(b1);
    // h2 = relu(h1 @ W2 + b2)
    gemm12_kernel<1024, 1><<<dim3(8, BSZ / 128), 256, gemm_smem>>>(b2);
    // S/T + coupling + logdet
    final_kernel<<<BSZ / 64, 256, final_smem>>>(bs, bt, x, out, logdet);
}

// round 16
// speedup vs baseline: 1.1295x; 1.0313x over previous
#include <cuda_runtime.h>
#include <cuda_bf16.h>
#include <cstdint>
#include <cstddef>

#define BSZ   65536
#define DD    256
#define CC    128
#define HH    1024
#define NSPLIT 128

// ---------------- device-global scratch (no allocation allowed) ----------------
__device__ __nv_bfloat16 g_A0_hi[(size_t)BSZ * 256];
__device__ __nv_bfloat16 g_A0_lo[(size_t)BSZ * 256];
__device__ __nv_bfloat16 g_h1_hi[(size_t)BSZ * HH];
__device__ __nv_bfloat16 g_h1_lo[(size_t)BSZ * HH];
__device__ __nv_bfloat16 g_h2_hi[(size_t)BSZ * HH];
__device__ __nv_bfloat16 g_h2_lo[(size_t)BSZ * HH];
__device__ __nv_bfloat16 g_W1t_hi[1024 * 256];   // [N=1024][K=256]
__device__ __nv_bfloat16 g_W1t_lo[1024 * 256];
__device__ __nv_bfloat16 g_W2t_hi[1024 * 1024];  // [N=1024][K=1024]
__device__ __nv_bfloat16 g_W2t_lo[1024 * 1024];
__device__ __nv_bfloat16 g_Wst_hi[256 * 1024];   // [N=256 interleaved S|T][K=1024]
__device__ __nv_bfloat16 g_Wst_lo[256 * 1024];

// ---------------- PTX helpers ----------------
__device__ __forceinline__ unsigned smem_u32(const void* p) {
    return (unsigned)__cvta_generic_to_shared(p);
}
__device__ __forceinline__ void cp16(unsigned dst, const void* src) {
    asm volatile("cp.async.cg.shared.global [%0], [%1], 16;\n" :: "r"(dst), "l"(src));
}
__device__ __forceinline__ void cp_commit() { asm volatile("cp.async.commit_group;\n"); }
__device__ __forceinline__ void cp_wait1()  { asm volatile("cp.async.wait_group 1;\n"); }

__device__ __forceinline__ void ldsm4(uint32_t& r0, uint32_t& r1, uint32_t& r2, uint32_t& r3,
                                      unsigned addr) {
    asm volatile("ldmatrix.sync.aligned.m8n8.x4.shared.b16 {%0,%1,%2,%3}, [%4];\n"
                 : "=r"(r0), "=r"(r1), "=r"(r2), "=r"(r3) : "r"(addr));
}

__device__ __forceinline__ void mma_bf16(float& c0, float& c1, float& c2, float& c3,
                                         uint32_t a0, uint32_t a1, uint32_t a2, uint32_t a3,
                                         uint32_t b0, uint32_t b1) {
    asm volatile(
        "mma.sync.aligned.m16n8k16.row.col.f32.bf16.bf16.f32 "
        "{%0,%1,%2,%3},{%4,%5,%6,%7},{%8,%9},{%0,%1,%2,%3};\n"
        : "+f"(c0), "+f"(c1), "+f"(c2), "+f"(c3)
        : "r"(a0), "r"(a1), "r"(a2), "r"(a3), "r"(b0), "r"(b1));
}

__device__ __forceinline__ void split2(float a, float b, uint32_t& hi, uint32_t& lo) {
    __nv_bfloat16 ha = __float2bfloat16_rn(a);
    __nv_bfloat16 hb = __float2bfloat16_rn(b);
    __nv_bfloat16 la = __float2bfloat16_rn(a - __bfloat162float(ha));
    __nv_bfloat16 lb = __float2bfloat16_rn(b - __bfloat162float(hb));
    hi = (uint32_t)__bfloat16_as_ushort(ha) | ((uint32_t)__bfloat16_as_ushort(hb) << 16);
    lo = (uint32_t)__bfloat16_as_ushort(la) | ((uint32_t)__bfloat16_as_ushort(lb) << 16);
}

// ---------------- merged pre-pass kernel (unchanged) ----------------
__global__ void prepass_kernel(const float* __restrict__ x, const float* __restrict__ cond,
                               const float* __restrict__ W1, const float* __restrict__ W2,
                               const float* __restrict__ Ws, const float* __restrict__ Wt) {
    const int b = blockIdx.x;
    const int tid = threadIdx.x;
    if (b < 65536) {
        size_t idx = (size_t)b * 256 + tid;
        int col = (int)(idx & 255);
        size_t row = idx >> 8;
        float v = (col < 128) ? x[row * DD + 2 * col] : cond[row * CC + (col - 128)];
        __nv_bfloat16 h = __float2bfloat16_rn(v);
        g_A0_hi[idx] = h;
        g_A0_lo[idx] = __float2bfloat16_rn(v - __bfloat162float(h));
    } else if (b < 66560) {
        size_t idx = (size_t)(b - 65536) * 256 + tid;    // over 1024*256
        int k = (int)(idx & 255);
        size_t n = idx >> 8;
        float v = W1[(size_t)k * 1024 + n];
        __nv_bfloat16 h = __float2bfloat16_rn(v);
        g_W1t_hi[idx] = h;
        g_W1t_lo[idx] = __float2bfloat16_rn(v - __bfloat162float(h));
    } else if (b < 70656) {
        size_t idx = (size_t)(b - 66560) * 256 + tid;    // over 1024*1024
        int k = (int)(idx & 1023);
        size_t n = idx >> 10;
        float v = W2[(size_t)k * 1024 + n];
        __nv_bfloat16 h = __float2bfloat16_rn(v);
        g_W2t_hi[idx] = h;
        g_W2t_lo[idx] = __float2bfloat16_rn(v - __bfloat162float(h));
    } else {
        size_t idx = (size_t)(b - 70656) * 256 + tid;    // over 256*1024
        int k = (int)(idx & 1023);
        int n = (int)(idx >> 10);
        const float* W = (n & 1) ? Wt : Ws;
        float v = W[(size_t)k * NSPLIT + (n >> 1)];
        __nv_bfloat16 h = __float2bfloat16_rn(v);
        g_Wst_hi[idx] = h;
        g_Wst_lo[idx] = __float2bfloat16_rn(v - __bfloat162float(h));
    }
}

// =====================================================================
// GEMM1/2 (unchanged from the winning 1561us version)
// =====================================================================
template <int K, int MODE>
__global__ void __launch_bounds__(256, 2)
gemm12_kernel(const float* __restrict__ bias) {
    constexpr int BM = 128, BN = 128, BK = 32;
    constexpr int NK = K / BK;
    constexpr int TILE_BYTES  = BM * 64;          // 8192 B
    constexpr int STAGE_BYTES = 4 * TILE_BYTES;   // 32768 B

    extern __shared__ __nv_bfloat16 sm[];
    const unsigned sbase = smem_u32(sm);

    const int tid = threadIdx.x;
    const int bx = blockIdx.x, by = blockIdx.y;
    const int warp = tid >> 5, lane = tid & 31;
    const int wm = warp & 3, wn = warp >> 2;
    const int g = lane >> 2, tg = lane & 3;

    const __nv_bfloat16* Ahi = MODE ? g_h1_hi : g_A0_hi;
    const __nv_bfloat16* Alo = MODE ? g_h1_lo : g_A0_lo;
    const __nv_bfloat16* Bhi = MODE ? g_W2t_hi : g_W1t_hi;
    const __nv_bfloat16* Blo = MODE ? g_W2t_lo : g_W1t_lo;

    float c[2][8][4];
#pragma unroll
    for (int mf = 0; mf < 2; mf++)
#pragma unroll
        for (int nf = 0; nf < 8; nf++)
#pragma unroll
            for (int r = 0; r < 4; r++) c[mf][nf][r] = 0.f;

    const int arow = (lane & 7) + ((lane >> 3) & 1) * 8;
    const int acb  = lane >> 4;
    const int brow = (lane & 7) + (lane >> 4) * 8;
    const int bcb  = (lane >> 3) & 1;
    int aRowB[2], aSw[2];
#pragma unroll
    for (int mf = 0; mf < 2; mf++) {
        int row = wm * 32 + mf * 16 + arow;
        aRowB[mf] = row * 64;
        aSw[mf] = (row >> 1) & 3;
    }
    int bRowB[4], bSw[4];
#pragma unroll
    for (int nfp = 0; nfp < 4; nfp++) {
        int row = wn * 64 + nfp * 16 + brow;
        bRowB[nfp] = row * 64;
        bSw[nfp] = (row >> 1) & 3;
    }

    auto load_tile = [&](int kt, int st) {
        const unsigned base = sbase + (unsigned)(st * STAGE_BYTES);
#pragma unroll
        for (int l = 0; l < 2; l++) {
            int e = l * 256 + tid;
            int r = e >> 2, ch = e & 3;
            int swc = ch ^ ((r >> 1) & 3);
            unsigned so = (unsigned)(r * 64 + swc * 16);
            size_t ga = (size_t)(by * BM + r) * K + kt * BK + ch * 8;
            size_t gb = (size_t)(bx * BN + r) * K + kt * BK + ch * 8;
            cp16(base + so, Ahi + ga);
            cp16(base + TILE_BYTES + so, Alo + ga);
            cp16(base + 2 * TILE_BYTES + so, Bhi + gb);
            cp16(base + 3 * TILE_BYTES + so, Blo + gb);
        }
    };

    load_tile(0, 0);
    cp_commit();
    load_tile(1, 1);
    cp_commit();

    int smain = 0, sload = 2;
    for (int kt = 0; kt < NK; kt++) {
        cp_wait1();
        __syncthreads();
        if (kt + 2 < NK) load_tile(kt + 2, sload);
        cp_commit();

        const unsigned stb = sbase + (unsigned)(smain * STAGE_BYTES);
#pragma unroll
        for (int ks = 0; ks < 2; ks++) {
            uint32_t ah[2][4], al[2][4];
#pragma unroll
            for (int mf = 0; mf < 2; mf++) {
                unsigned ach = (unsigned)(((ks * 2 + acb) ^ aSw[mf]) << 4);
                ldsm4(ah[mf][0], ah[mf][1], ah[mf][2], ah[mf][3],
                      stb + (unsigned)aRowB[mf] + ach);
                ldsm4(al[mf][0], al[mf][1], al[mf][2], al[mf][3],
                      stb + (unsigned)TILE_BYTES + (unsigned)aRowB[mf] + ach);
            }
#pragma unroll
            for (int nfp = 0; nfp < 4; nfp++) {
                unsigned bch = (unsigned)(((ks * 2 + bcb) ^ bSw[nfp]) << 4);
                uint32_t bh[4], bl[4];
                ldsm4(bh[0], bh[1], bh[2], bh[3],
                      stb + (unsigned)(2 * TILE_BYTES) + (unsigned)bRowB[nfp] + bch);
                ldsm4(bl[0], bl[1], bl[2], bl[3],
                      stb + (unsigned)(3 * TILE_BYTES) + (unsigned)bRowB[nfp] + bch);
#pragma unroll
                for (int sub = 0; sub < 2; sub++) {
                    int nf = nfp * 2 + sub;
#pragma unroll
                    for (int mf = 0; mf < 2; mf++) {
                        mma_bf16(c[mf][nf][0], c[mf][nf][1], c[mf][nf][2], c[mf][nf][3],
                                 ah[mf][0], ah[mf][1], ah[mf][2], ah[mf][3],
                                 bh[2 * sub], bh[2 * sub + 1]);
                        mma_bf16(c[mf][nf][0], c[mf][nf][1], c[mf][nf][2], c[mf][nf][3],
                                 ah[mf][0], ah[mf][1], ah[mf][2], ah[mf][3],
                                 bl[2 * sub], bl[2 * sub + 1]);
                        mma_bf16(c[mf][nf][0], c[mf][nf][1], c[mf][nf][2], c[mf][nf][3],
                                 al[mf][0], al[mf][1], al[mf][2], al[mf][3],
                                 bh[2 * sub], bh[2 * sub + 1]);
                    }
                }
            }
        }
        smain = (smain == 2) ? 0 : smain + 1;
        sload = (sload == 2) ? 0 : sload + 1;
    }

    __nv_bfloat16* Ohi = MODE ? g_h2_hi : g_h1_hi;
    __nv_bfloat16* Olo = MODE ? g_h2_lo : g_h1_lo;
#pragma unroll
    for (int mf = 0; mf < 2; mf++) {
        int r0 = by * BM + wm * 32 + mf * 16 + g;
#pragma unroll
        for (int nf = 0; nf < 8; nf++) {
            int nc = bx * BN + wn * 64 + nf * 8 + 2 * tg;
            float2 bv = *(const float2*)&bias[nc];
            float v0 = fmaxf(c[mf][nf][0] + bv.x, 0.f);
            float v1 = fmaxf(c[mf][nf][1] + bv.y, 0.f);
            float v2 = fmaxf(c[mf][nf][2] + bv.x, 0.f);
            float v3 = fmaxf(c[mf][nf][3] + bv.y, 0.f);
            uint32_t hi, lo;
            size_t o0 = (size_t)r0 * HH + nc;
            split2(v0, v1, hi, lo);
            *(uint32_t*)(Ohi + o0) = hi;
            *(uint32_t*)(Olo + o0) = lo;
            size_t o1 = (size_t)(r0 + 8) * HH + nc;
            split2(v2, v3, hi, lo);
            *(uint32_t*)(Ohi + o1) = hi;
            *(uint32_t*)(Olo + o1) = lo;
        }
    }
}

// =====================================================================
// GEMM3: [S|T] = h2 @ Wst^T; coupling + logdet. CTA 64x256, 8 warps (2x4).
// Split pipelines: A (h2, DRAM-latency) 3 stages / distance 2;
//                  B (Wst, L2-resident) 2 stages / distance 1.
// Per-iter commits: [B(kt+1)] then [A(kt+2)] -> wait_group 1 is exact.
// Swizzled unpadded 64B rows (same scheme as gemm12).
// =====================================================================
__global__ void __launch_bounds__(256, 2)
final_kernel(const float* __restrict__ bs, const float* __restrict__ bt,
             const float* __restrict__ x, float* __restrict__ out,
             float* __restrict__ logdet) {
    constexpr int BM = 64, BN = 256, BK = 32;
    constexpr int K = HH, NK = K / BK;
    constexpr int A_TILE = BM * 64;               // 4096 B (one of hi/lo)
    constexpr int A_STAGE = 2 * A_TILE;           // 8192 B
    constexpr int B_TILE = BN * 64;               // 16384 B
    constexpr int B_STAGE = 2 * B_TILE;           // 32768 B
    constexpr int OFF_B = 3 * A_STAGE;            // 24576
    constexpr int OFF_DET = OFF_B + 2 * B_STAGE;  // 90112

    extern __shared__ char smc[];
    float* sdet = (float*)(smc + OFF_DET);        // 64 floats
    const unsigned sbase = smem_u32(smc);

    const int tid = threadIdx.x;
    const int by = blockIdx.x;
    const int warp = tid >> 5, lane = tid & 31;
    const int wm = warp & 1, wn = warp >> 1;      // 2x4 warps, warp tile 32x64
    const int g = lane >> 2, tg = lane & 3;

    if (tid < 64) sdet[tid] = 0.f;

    float c[2][8][4];
#pragma unroll
    for (int mf = 0; mf < 2; mf++)
#pragma unroll
        for (int nf = 0; nf < 8; nf++)
#pragma unroll
            for (int r = 0; r < 4; r++) c[mf][nf][r] = 0.f;

    const int arow = (lane & 7) + ((lane >> 3) & 1) * 8;
    const int acb  = lane >> 4;
    const int brow = (lane & 7) + (lane >> 4) * 8;
    const int bcb  = (lane >> 3) & 1;
    int aRowB[2], aSw[2];
#pragma unroll
    for (int mf = 0; mf < 2; mf++) {
        int row = wm * 32 + mf * 16 + arow;
        aRowB[mf] = row * 64;
        aSw[mf] = (row >> 1) & 3;
    }
    int bRowB[4], bSw[4];
#pragma unroll
    for (int nfp = 0; nfp < 4; nfp++) {
        int row = wn * 64 + nfp * 16 + brow;
        bRowB[nfp] = row * 64;
        bSw[nfp] = (row >> 1) & 3;
    }

    // A loader: 64 rows x 4 chunks = 256 entries, 1 per thread (hi + lo)
    auto load_a = [&](int kt, int st) {
        const unsigned base = sbase + (unsigned)(st * A_STAGE);
        int r = tid >> 2, ch = tid & 3;
        int swc = ch ^ ((r >> 1) & 3);
        unsigned so = (unsigned)(r * 64 + swc * 16);
        size_t ga = (size_t)(by * BM + r) * K + kt * BK + ch * 8;
        cp16(base + so, g_h2_hi + ga);
        cp16(base + A_TILE + so, g_h2_lo + ga);
    };
    // B loader: 256 rows x 4 chunks = 1024 entries, 4 per thread (hi + lo)
    auto load_b = [&](int kt, int st) {
        const unsigned base = sbase + (unsigned)(OFF_B + st * B_STAGE);
#pragma unroll
        for (int l = 0; l < 4; l++) {
            int e = l * 256 + tid;
            int r = e >> 2, ch = e & 3;
            int swc = ch ^ ((r >> 1) & 3);
            unsigned so = (unsigned)(r * 64 + swc * 16);
            size_t gb = (size_t)r * K + kt * BK + ch * 8;
            cp16(base + so, g_Wst_hi + gb);
            cp16(base + B_TILE + so, g_Wst_lo + gb);
        }
    };

    // prologue: groups [B0][A0][A1]
    load_b(0, 0);
    cp_commit();
    load_a(0, 0);
    cp_commit();
    load_a(1, 1);
    cp_commit();

    for (int kt = 0; kt < NK; kt++) {
        const int amain = kt % 3;
        const int bmain = kt & 1;
        cp_wait1();            // B(kt) and A(kt) landed; A(kt+1) may be in flight
        __syncthreads();       // stages being overwritten were consumed at kt-1
        if (kt + 1 < NK) load_b(kt + 1, (kt + 1) & 1);
        cp_commit();
        if (kt + 2 < NK) load_a(kt + 2, (kt + 2) % 3);
        cp_commit();

        const unsigned astb = sbase + (unsigned)(amain * A_STAGE);
        const unsigned bstb = sbase + (unsigned)(OFF_B + bmain * B_STAGE);
#pragma unroll
        for (int ks = 0; ks < 2; ks++) {
            uint32_t ah[2][4], al[2][4];
#pragma unroll
            for (int mf = 0; mf < 2; mf++) {
                unsigned ach = (unsigned)(((ks * 2 + acb) ^ aSw[mf]) << 4);
                ldsm4(ah[mf][0], ah[mf][1], ah[mf][2], ah[mf][3],
                      astb + (unsigned)aRowB[mf] + ach);
                ldsm4(al[mf][0], al[mf][1], al[mf][2], al[mf][3],
                      astb + (unsigned)A_TILE + (unsigned)aRowB[mf] + ach);
            }
#pragma unroll
            for (int nfp = 0; nfp < 4; nfp++) {
                unsigned bch = (unsigned)(((ks * 2 + bcb) ^ bSw[nfp]) << 4);
                uint32_t bh[4], bl[4];
                ldsm4(bh[0], bh[1], bh[2], bh[3],
                      bstb + (unsigned)bRowB[nfp] + bch);
                ldsm4(bl[0], bl[1], bl[2], bl[3],
                      bstb + (unsigned)B_TILE + (unsigned)bRowB[nfp] + bch);
#pragma unroll
                for (int sub = 0; sub < 2; sub++) {
                    int nf = nfp * 2 + sub;
#pragma unroll
                    for (int mf = 0; mf < 2; mf++) {
                        mma_bf16(c[mf][nf][0], c[mf][nf][1], c[mf][nf][2], c[mf][nf][3],
                                 ah[mf][0], ah[mf][1], ah[mf][2], ah[mf][3],
                                 bh[2 * sub], bh[2 * sub + 1]);
                        mma_bf16(c[mf][nf][0], c[mf][nf][1], c[mf][nf][2], c[mf][nf][3],
                                 ah[mf][0], ah[mf][1], ah[mf][2], ah[mf][3],
                                 bl[2 * sub], bl[2 * sub + 1]);
                        mma_bf16(c[mf][nf][0], c[mf][nf][1], c[mf][nf][2], c[mf][nf][3],
                                 al[mf][0], al[mf][1], al[mf][2], al[mf][3],
                                 bh[2 * sub], bh[2 * sub + 1]);
                    }
                }
            }
        }
    }

    // coupling epilogue: even col = S, odd col = T (interleaved Wst)
#pragma unroll
    for (int mf = 0; mf < 2; mf++) {
        int lr = wm * 32 + mf * 16 + g;
        size_t r0 = (size_t)(by * BM + lr);
        float ld0 = 0.f, ld1 = 0.f;
#pragma unroll
        for (int nf = 0; nf < 8; nf++) {
            int nc = wn * 64 + nf * 8 + 2 * tg;   // even col in [0,256)
            int j = nc >> 1;                      // pair index in [0,128)
            float bsv = __ldg(&bs[j]);
            float btv = __ldg(&bt[j]);

            float ls0 = tanhf(c[mf][nf][0] + bsv);
            float t0  = c[mf][nf][1] + btv;
            float2 xv0 = *(const float2*)&x[r0 * DD + 2 * j];
            *(float2*)&out[r0 * DD + 2 * j] =
                make_float2(xv0.x, xv0.y * expf(ls0) + t0);
            ld0 += ls0;

            float ls1 = tanhf(c[mf][nf][2] + bsv);
            float t1  = c[mf][nf][3] + btv;
            float2 xv1 = *(const float2*)&x[(r0 + 8) * DD + 2 * j];
            *(float2*)&out[(r0 + 8) * DD + 2 * j] =
                make_float2(xv1.x, xv1.y * expf(ls1) + t1);
            ld1 += ls1;
        }
        atomicAdd(&sdet[lr], ld0);
        atomicAdd(&sdet[lr + 8], ld1);
    }
    __syncthreads();
    if (tid < 64) logdet[(size_t)by * BM + tid] = sdet[tid];
}

// ---------------- launch ----------------
extern "C" void kernel_launch(void* const* d_in, const int* in_sizes, int n_in,
                              void* d_out, int out_size) {
    const float* x    = (const float*)d_in[0];
    const float* cond = (const float*)d_in[1];
    const float* W1   = (const float*)d_in[2];
    const float* b1   = (const float*)d_in[3];
    const float* W2   = (const float*)d_in[4];
    const float* b2   = (const float*)d_in[5];
    const float* Ws   = (const float*)d_in[6];
    const float* bs   = (const float*)d_in[7];
    const float* Wt   = (const float*)d_in[8];
    const float* bt   = (const float*)d_in[9];

    float* out = (float*)d_out;
    float* logdet = out + ((size_t)out_size - BSZ);

    const int gemm_smem  = 3 * 4 * 128 * 64;          // 98304
    const int final_smem = 3 * 8192 + 2 * 32768 + 256; // 90368

    cudaFuncSetAttribute(gemm12_kernel<256, 0>,
                         cudaFuncAttributeMaxDynamicSharedMemorySize, gemm_smem);
    cudaFuncSetAttribute(gemm12_kernel<1024, 1>,
                         cudaFuncAttributeMaxDynamicSharedMemorySize, gemm_smem);
    cudaFuncSetAttribute(final_kernel,
                         cudaFuncAttributeMaxDynamicSharedMemorySize, final_smem);

    // merged pre-pass: split/transpose all operands (71680 blocks)
    prepass_kernel<<<71680, 256>>>(x, cond, W1, W2, Ws, Wt);

    // h1 = relu([x_even|cond] @ W1 + b1)
    gemm12_kernel<256, 0><<<dim3(8, BSZ / 128), 256, gemm_smem>>>(b1);
    // h2 = relu(h1 @ W2 + b2)
    gemm12_kernel<1024, 1><<<dim3(8, BSZ / 128), 256, gemm_smem>>>(b2);
    // S/T + coupling + logdet
    final_kernel<<<BSZ / 64, 256, final_smem>>>(bs, bt, x, out, logdet);
}